// round 3
// baseline (speedup 1.0000x reference)
#include <cuda_runtime.h>
#include <math.h>

// Problem dims (fixed by the dataset): B=2, V=8, T=512, D=1024, H=4096.
// M = B*V*T = 8192 token rows.
#define M_TOK 8192
#define DIM   1024
#define HID   4096

#define BM 128
#define BN 128
#define BK 16
#define TM 8
#define TN 8

// Scratch (device globals are the sanctioned workaround for no-alloc rule).
__device__ float g_z[(size_t)M_TOK * DIM];   // 32 MB
__device__ float g_h[(size_t)M_TOK * HID];   // 128 MB

__device__ __forceinline__ float gelu_exact(float v) {
    return 0.5f * v * (1.0f + erff(v * 0.70710678118654752f));
}

// C[M,N] = A[M,K] @ B[K,N] (+bias, +gelu depending on OP)
// OP=0: plain   OP=1: bias + exact GELU   OP=2: bias
template <int OP>
__global__ __launch_bounds__(256) void gemm_kernel(
    const float* __restrict__ A, const float* __restrict__ B,
    const float* __restrict__ bias, float* __restrict__ C,
    int M, int N, int K)
{
    __shared__ float As[BK][BM];   // A staged transposed: As[k][m]
    __shared__ float Bs[BK][BN];

    const int bx = blockIdx.x;     // N tile
    const int by = blockIdx.y;     // M tile
    const int tid = threadIdx.x;
    const int tx = tid & 15;       // 16 cols of threads
    const int ty = tid >> 4;       // 16 rows of threads

    const float* Ab = A + (size_t)by * BM * K;
    const float* Bb = B + (size_t)bx * BN;

    float acc[TM][TN];
#pragma unroll
    for (int i = 0; i < TM; i++)
#pragma unroll
        for (int j = 0; j < TN; j++) acc[i][j] = 0.0f;

    // A-load mapping: thread loads rows (tid>>2) and (tid>>2)+64, k-quad (tid&3)*4
    const int arow = tid >> 2;          // 0..63
    const int akq  = (tid & 3) * 4;     // 0,4,8,12
    // B-load mapping: passes p: idx = p*256+tid -> row idx>>5 (+8), col4 (idx&31)*4
    const int brow = tid >> 5;          // 0..7
    const int bcol = (tid & 31) * 4;    // 0..124

    for (int kt = 0; kt < K; kt += BK) {
        // Stage A tile (transposed)
#pragma unroll
        for (int p = 0; p < 2; p++) {
            const int r = arow + p * 64;
            float4 v = *reinterpret_cast<const float4*>(Ab + (size_t)r * K + kt + akq);
            As[akq + 0][r] = v.x;
            As[akq + 1][r] = v.y;
            As[akq + 2][r] = v.z;
            As[akq + 3][r] = v.w;
        }
        // Stage B tile
#pragma unroll
        for (int p = 0; p < 2; p++) {
            const int r = brow + p * 8;
            float4 v = *reinterpret_cast<const float4*>(Bb + (size_t)(kt + r) * N + bcol);
            *reinterpret_cast<float4*>(&Bs[r][bcol]) = v;
        }
        __syncthreads();

#pragma unroll
        for (int k = 0; k < BK; k++) {
            float a[TM], b[TN];
            float4 a0 = *reinterpret_cast<const float4*>(&As[k][ty * TM]);
            float4 a1 = *reinterpret_cast<const float4*>(&As[k][ty * TM + 4]);
            float4 b0 = *reinterpret_cast<const float4*>(&Bs[k][tx * TN]);
            float4 b1 = *reinterpret_cast<const float4*>(&Bs[k][tx * TN + 4]);
            a[0]=a0.x; a[1]=a0.y; a[2]=a0.z; a[3]=a0.w;
            a[4]=a1.x; a[5]=a1.y; a[6]=a1.z; a[7]=a1.w;
            b[0]=b0.x; b[1]=b0.y; b[2]=b0.z; b[3]=b0.w;
            b[4]=b1.x; b[5]=b1.y; b[6]=b1.z; b[7]=b1.w;
#pragma unroll
            for (int i = 0; i < TM; i++)
#pragma unroll
                for (int j = 0; j < TN; j++)
                    acc[i][j] = fmaf(a[i], b[j], acc[i][j]);
        }
        __syncthreads();
    }

    // Epilogue
#pragma unroll
    for (int i = 0; i < TM; i++) {
        const int row = by * BM + ty * TM + i;
#pragma unroll
        for (int j = 0; j < TN; j += 4) {
            const int col = bx * BN + tx * TN + j;
            float4 v;
            v.x = acc[i][j + 0];
            v.y = acc[i][j + 1];
            v.z = acc[i][j + 2];
            v.w = acc[i][j + 3];
            if (OP >= 1) {
                v.x += bias[col + 0];
                v.y += bias[col + 1];
                v.z += bias[col + 2];
                v.w += bias[col + 3];
            }
            if (OP == 1) {
                v.x = gelu_exact(v.x);
                v.y = gelu_exact(v.y);
                v.z = gelu_exact(v.z);
                v.w = gelu_exact(v.w);
            }
            *reinterpret_cast<float4*>(C + (size_t)row * N + col) = v;
        }
    }
}

// Fused LayerNorm + residual: out[row,:] = z[row,:] + tanh(alpha)*LN(y[row,:])
// y lives in `out` already (written by gemm3); overwritten in place (block-local).
__global__ __launch_bounds__(256) void ln_residual_kernel(
    const float* __restrict__ Z,
    const float* __restrict__ gamma, const float* __restrict__ beta,
    const float* __restrict__ alpha, float* __restrict__ out)
{
    const int row = blockIdx.x;
    const int tid = threadIdx.x;
    float4* orow = reinterpret_cast<float4*>(out + (size_t)row * DIM);
    const float4* zrow = reinterpret_cast<const float4*>(Z + (size_t)row * DIM);

    float4 v = orow[tid];   // y values

    __shared__ float red1[8];
    __shared__ float red2[8];

    // mean
    float s = v.x + v.y + v.z + v.w;
#pragma unroll
    for (int o = 16; o > 0; o >>= 1) s += __shfl_xor_sync(0xffffffffu, s, o);
    if ((tid & 31) == 0) red1[tid >> 5] = s;
    __syncthreads();
    float tot = 0.0f;
#pragma unroll
    for (int i = 0; i < 8; i++) tot += red1[i];
    const float mu = tot * (1.0f / (float)DIM);

    const float dx = v.x - mu, dy = v.y - mu, dz = v.z - mu, dw = v.w - mu;
    float ss = dx * dx + dy * dy + dz * dz + dw * dw;
#pragma unroll
    for (int o = 16; o > 0; o >>= 1) ss += __shfl_xor_sync(0xffffffffu, ss, o);
    if ((tid & 31) == 0) red2[tid >> 5] = ss;
    __syncthreads();
    float tot2 = 0.0f;
#pragma unroll
    for (int i = 0; i < 8; i++) tot2 += red2[i];
    const float rstd = rsqrtf(tot2 * (1.0f / (float)DIM) + 1e-5f);

    const float4 g  = reinterpret_cast<const float4*>(gamma)[tid];
    const float4 b  = reinterpret_cast<const float4*>(beta)[tid];
    const float4 al = reinterpret_cast<const float4*>(alpha)[tid];
    const float4 z4 = zrow[tid];

    float4 o4;
    o4.x = z4.x + tanhf(al.x) * (dx * rstd * g.x + b.x);
    o4.y = z4.y + tanhf(al.y) * (dy * rstd * g.y + b.y);
    o4.z = z4.z + tanhf(al.z) * (dz * rstd * g.z + b.z);
    o4.w = z4.w + tanhf(al.w) * (dw * rstd * g.w + b.w);
    orow[tid] = o4;
}

extern "C" void kernel_launch(void* const* d_in, const int* in_sizes, int n_in,
                              void* d_out, int out_size)
{
    const float* x       = (const float*)d_in[0];  // [B,V,T,D] = [8192,1024]
    const float* theta_Q = (const float*)d_in[1];  // [1024,1024]
    const float* W1      = (const float*)d_in[2];  // [1024,4096]
    const float* b1      = (const float*)d_in[3];  // [4096]
    const float* W2      = (const float*)d_in[4];  // [4096,1024]
    const float* b2      = (const float*)d_in[5];  // [1024]
    const float* gamma   = (const float*)d_in[6];  // [1024]
    const float* beta    = (const float*)d_in[7];  // [1024]
    const float* alpha   = (const float*)d_in[8];  // [1,1024]
    float* out = (float*)d_out;                    // [8192,1024]

    float *pz = nullptr, *ph = nullptr;
    cudaGetSymbolAddress((void**)&pz, g_z);
    cudaGetSymbolAddress((void**)&ph, g_h);

    // z = x @ theta_Q                       [8192,1024]
    gemm_kernel<0><<<dim3(DIM / BN, M_TOK / BM), 256>>>(x, theta_Q, nullptr, pz,
                                                        M_TOK, DIM, DIM);
    // h = gelu(z @ W1 + b1)                 [8192,4096]
    gemm_kernel<1><<<dim3(HID / BN, M_TOK / BM), 256>>>(pz, W1, b1, ph,
                                                        M_TOK, HID, DIM);
    // y = h @ W2 + b2  -> write into d_out  [8192,1024]
    gemm_kernel<2><<<dim3(DIM / BN, M_TOK / BM), 256>>>(ph, W2, b2, out,
                                                        M_TOK, DIM, HID);
    // out = z + tanh(alpha) * LN(y)   (in-place over d_out)
    ln_residual_kernel<<<M_TOK, 256>>>(pz, gamma, beta, alpha, out);
}

// round 8
// speedup vs baseline: 2.5203x; 2.5203x over previous
#include <cuda_runtime.h>
#include <cuda_bf16.h>
#include <math.h>
#include <stdint.h>

// Dims fixed by dataset: B=2,V=8,T=512,D=1024,H=4096 -> M=8192 rows.
#define M_TOK 8192
#define DIM   1024
#define HID   4096

// ---------------- scratch (device globals: sanctioned no-alloc workaround) ----
__device__ float    g_z [(size_t)M_TOK * DIM];   // z fp32 (for residual)
__device__ uint16_t g_xh[(size_t)M_TOK * DIM];
__device__ uint16_t g_xl[(size_t)M_TOK * DIM];
__device__ uint16_t g_zh[(size_t)M_TOK * DIM];
__device__ uint16_t g_zl[(size_t)M_TOK * DIM];
__device__ uint16_t g_hh[(size_t)M_TOK * HID];
__device__ uint16_t g_hl[(size_t)M_TOK * HID];
__device__ uint16_t g_th [(size_t)DIM * DIM];    // theta^T hi/lo [N=D,K=D]
__device__ uint16_t g_tl [(size_t)DIM * DIM];
__device__ uint16_t g_w1h[(size_t)HID * DIM];    // W1^T [H,D]
__device__ uint16_t g_w1l[(size_t)HID * DIM];
__device__ uint16_t g_w2h[(size_t)DIM * HID];    // W2^T [D,H]
__device__ uint16_t g_w2l[(size_t)DIM * HID];

// ---------------- helpers -------------------------------------------------------
__device__ __forceinline__ uint32_t smem_u32(const void* p) {
    uint32_t a;
    asm("{ .reg .u64 t; cvta.to.shared.u64 t, %1; cvt.u32.u64 %0, t; }" : "=r"(a) : "l"(p));
    return a;
}

__device__ __forceinline__ float gelu_exact(float v) {
    return 0.5f * v * (1.0f + erff(v * 0.70710678118654752f));
}

__device__ __forceinline__ void split_bf(float v, uint16_t& h, uint16_t& l) {
    __nv_bfloat16 bh = __float2bfloat16_rn(v);
    float fh = __bfloat162float(bh);
    __nv_bfloat16 bl = __float2bfloat16_rn(v - fh);
    h = *reinterpret_cast<uint16_t*>(&bh);
    l = *reinterpret_cast<uint16_t*>(&bl);
}

__device__ __forceinline__ void ldsm4(uint32_t (&r)[4], uint32_t addr) {
    asm volatile("ldmatrix.sync.aligned.m8n8.x4.shared.b16 {%0,%1,%2,%3}, [%4];"
        : "=r"(r[0]), "=r"(r[1]), "=r"(r[2]), "=r"(r[3]) : "r"(addr));
}

__device__ __forceinline__ void mma_bf16(float (&c)[4], const uint32_t (&a)[4],
                                         uint32_t b0, uint32_t b1) {
    asm volatile(
        "mma.sync.aligned.m16n8k16.row.col.f32.bf16.bf16.f32 "
        "{%0,%1,%2,%3}, {%4,%5,%6,%7}, {%8,%9}, {%0,%1,%2,%3};"
        : "+f"(c[0]), "+f"(c[1]), "+f"(c[2]), "+f"(c[3])
        : "r"(a[0]), "r"(a[1]), "r"(a[2]), "r"(a[3]), "r"(b0), "r"(b1));
}

#define CP16(dst, src) \
    asm volatile("cp.async.cg.shared.global [%0], [%1], 16;" :: "r"(dst), "l"(src))
#define CP_COMMIT() asm volatile("cp.async.commit_group;")
#define CP_WAIT2()  asm volatile("cp.async.wait_group 2;")

// ---------------- pre-pass kernels ---------------------------------------------
__global__ __launch_bounds__(256) void convert_split_kernel(
    const float* __restrict__ in, uint16_t* __restrict__ hi, uint16_t* __restrict__ lo)
{
    size_t i = ((size_t)blockIdx.x * 256 + threadIdx.x) * 4;
    float4 v = *reinterpret_cast<const float4*>(in + i);
    ushort4 h, l;
    split_bf(v.x, h.x, l.x);
    split_bf(v.y, h.y, l.y);
    split_bf(v.z, h.z, l.z);
    split_bf(v.w, h.w, l.w);
    *reinterpret_cast<ushort4*>(hi + i) = h;
    *reinterpret_cast<ushort4*>(lo + i) = l;
}

// W is [K,N] fp32 row-major; outputs W^T hi/lo as [N,K] bf16-bits.
__global__ __launch_bounds__(256) void transpose_split_kernel(
    const float* __restrict__ W, uint16_t* __restrict__ oh, uint16_t* __restrict__ ol,
    int K, int N)
{
    __shared__ float tile[32][33];
    const int tx = threadIdx.x, ty = threadIdx.y;
    const int n0 = blockIdx.x * 32, k0 = blockIdx.y * 32;
#pragma unroll
    for (int i = 0; i < 4; i++)
        tile[ty + i * 8][tx] = W[(size_t)(k0 + ty + i * 8) * N + (n0 + tx)];
    __syncthreads();
#pragma unroll
    for (int i = 0; i < 4; i++) {
        float v = tile[tx][ty + i * 8];
        uint16_t h, l;
        split_bf(v, h, l);
        size_t o = (size_t)(n0 + ty + i * 8) * K + (k0 + tx);
        oh[o] = h;
        ol[o] = l;
    }
}

// ---------------- mma.sync GEMM -------------------------------------------------
// C[M,N] = A @ B^T; A [M,K] hi/lo bf16 K-major, B [N,K] hi/lo bf16 K-major.
// 3-term split: Ahi*Bhi + Ahi*Blo + Alo*Bhi, fp32 accumulators.
// CTA tile 128x128, BK=32, 8 warps (warp tile 32m x 64n), 3-stage cp.async.
// Smem per stage (32KB): Ahi[0,8K) Alo[8K,16K) Bhi[16K,24K) Blo[24K,32K)
// Tile layout: 128 rows x 64B (32 bf16), 16B chunk c stored at c ^ ((row>>1)&3).
// OP 0: out fp32 + split          (z)
// OP 1: +bias, exact GELU, split  (h)
// OP 2: +bias, out fp32           (y -> d_out)

#define STAGE_BYTES 32768
#define SMEM_TOTAL  (3 * STAGE_BYTES)

template <int OP>
__global__ __launch_bounds__(256, 1) void gemm_mma(
    const uint16_t* __restrict__ Ah, const uint16_t* __restrict__ Al,
    const uint16_t* __restrict__ Bh, const uint16_t* __restrict__ Bl,
    const float* __restrict__ bias,
    float* __restrict__ outF, uint16_t* __restrict__ outH, uint16_t* __restrict__ outL,
    int K, int N)
{
    extern __shared__ __align__(1024) char smem[];
    const uint32_t sb = smem_u32(smem);
    const int tid = threadIdx.x;
    const int wid = tid >> 5, lane = tid & 31;
    const int bx = blockIdx.x, by = blockIdx.y;
    const int NKC = K >> 5;

    const uint16_t* A0h = Ah + (size_t)(by * 128) * K;
    const uint16_t* A0l = Al + (size_t)(by * 128) * K;
    const uint16_t* B0h = Bh + (size_t)(bx * 128) * K;
    const uint16_t* B0l = Bl + (size_t)(bx * 128) * K;

    // staging: 512 chunk-slots per tile, 2 per thread per tile
    const int srow0 = tid >> 2, sc = tid & 3;          // id = tid
    const int srow1 = (tid + 256) >> 2;                // id = tid + 256 (same sc)
    const uint32_t sd0 = (uint32_t)(srow0 * 64 + ((sc ^ ((srow0 >> 1) & 3)) << 4));
    const uint32_t sd1 = (uint32_t)(srow1 * 64 + ((sc ^ ((srow1 >> 1) & 3)) << 4));

    auto issue = [&](int s) {
        if (s < NKC) {
            const int kof = s * 32 + sc * 8;
            const uint32_t base = sb + (uint32_t)(s % 3) * STAGE_BYTES;
            const size_t o0 = (size_t)srow0 * K + kof;
            const size_t o1 = (size_t)srow1 * K + kof;
            CP16(base + sd0,         A0h + o0);
            CP16(base + sd1,         A0h + o1);
            CP16(base + 8192  + sd0, A0l + o0);
            CP16(base + 8192  + sd1, A0l + o1);
            CP16(base + 16384 + sd0, B0h + o0);
            CP16(base + 16384 + sd1, B0h + o1);
            CP16(base + 24576 + sd0, B0l + o0);
            CP16(base + 24576 + sd1, B0l + o1);
        }
        CP_COMMIT();
    };

    issue(0);
    issue(1);
    issue(2);

    const int wm = wid >> 1;          // 0..3 -> m offset wm*32
    const int wn = wid & 1;           // 0..1 -> n offset wn*64
    // ldmatrix lane address components
    const int a_r = (lane & 7) + ((lane >> 3) & 1) * 8;  // row-in-frag for A
    const int a_c = lane >> 4;                           // +chunk for A
    const int b_r = (lane & 7) + ((lane >> 4) << 3);     // row-in-frag for B
    const int b_c = (lane >> 3) & 1;                     // +chunk for B

    float c[2][8][4];
#pragma unroll
    for (int mf = 0; mf < 2; mf++)
#pragma unroll
        for (int nf = 0; nf < 8; nf++)
#pragma unroll
            for (int j = 0; j < 4; j++) c[mf][nf][j] = 0.0f;

    for (int kc = 0; kc < NKC; kc++) {
        CP_WAIT2();
        __syncthreads();
        const uint32_t buf = sb + (uint32_t)(kc % 3) * STAGE_BYTES;
#pragma unroll
        for (int ks = 0; ks < 2; ks++) {
            uint32_t ahf[2][4], alf[2][4];
#pragma unroll
            for (int mf = 0; mf < 2; mf++) {
                const int r = wm * 32 + mf * 16 + a_r;
                const uint32_t ad = buf + (uint32_t)(r * 64 +
                                   (((2 * ks + a_c) ^ ((r >> 1) & 3)) << 4));
                ldsm4(ahf[mf], ad);
                ldsm4(alf[mf], ad + 8192);
            }
#pragma unroll
            for (int g = 0; g < 4; g++) {
                const int r = wn * 64 + g * 16 + b_r;
                const uint32_t bd = buf + 16384 + (uint32_t)(r * 64 +
                                   (((2 * ks + b_c) ^ ((r >> 1) & 3)) << 4));
                uint32_t b[4];
                ldsm4(b, bd);          // Bhi
#pragma unroll
                for (int mf = 0; mf < 2; mf++) {
                    mma_bf16(c[mf][2 * g + 0], ahf[mf], b[0], b[1]);
                    mma_bf16(c[mf][2 * g + 1], ahf[mf], b[2], b[3]);
                    mma_bf16(c[mf][2 * g + 0], alf[mf], b[0], b[1]);
                    mma_bf16(c[mf][2 * g + 1], alf[mf], b[2], b[3]);
                }
                ldsm4(b, bd + 8192);   // Blo
#pragma unroll
                for (int mf = 0; mf < 2; mf++) {
                    mma_bf16(c[mf][2 * g + 0], ahf[mf], b[0], b[1]);
                    mma_bf16(c[mf][2 * g + 1], ahf[mf], b[2], b[3]);
                }
            }
        }
        __syncthreads();
        issue(kc + 3);
    }

    // ---- epilogue: fragments -> GMEM (coalesced 32B sectors per lane-quad) ----
    const int r0 = by * 128 + wm * 32 + (lane >> 2);
    const int c0 = bx * 128 + wn * 64 + (lane & 3) * 2;

#pragma unroll
    for (int mf = 0; mf < 2; mf++) {
#pragma unroll
        for (int nf = 0; nf < 8; nf++) {
            const int col = c0 + nf * 8;
            float bv0 = 0.0f, bv1 = 0.0f;
            if (OP >= 1) { bv0 = bias[col]; bv1 = bias[col + 1]; }
#pragma unroll
            for (int half = 0; half < 2; half++) {
                const int row = r0 + mf * 16 + half * 8;
                float v0 = c[mf][nf][2 * half + 0];
                float v1 = c[mf][nf][2 * half + 1];
                const size_t o = (size_t)row * N + col;
                if (OP == 0) {
                    *reinterpret_cast<float2*>(outF + o) = make_float2(v0, v1);
                    uint16_t h0, l0, h1, l1;
                    split_bf(v0, h0, l0);
                    split_bf(v1, h1, l1);
                    *reinterpret_cast<uint32_t*>(outH + o) = (uint32_t)h0 | ((uint32_t)h1 << 16);
                    *reinterpret_cast<uint32_t*>(outL + o) = (uint32_t)l0 | ((uint32_t)l1 << 16);
                } else if (OP == 1) {
                    v0 = gelu_exact(v0 + bv0);
                    v1 = gelu_exact(v1 + bv1);
                    uint16_t h0, l0, h1, l1;
                    split_bf(v0, h0, l0);
                    split_bf(v1, h1, l1);
                    *reinterpret_cast<uint32_t*>(outH + o) = (uint32_t)h0 | ((uint32_t)h1 << 16);
                    *reinterpret_cast<uint32_t*>(outL + o) = (uint32_t)l0 | ((uint32_t)l1 << 16);
                } else {
                    *reinterpret_cast<float2*>(outF + o) = make_float2(v0 + bv0, v1 + bv1);
                }
            }
        }
    }
}

// ---------------- LayerNorm + residual -----------------------------------------
__global__ __launch_bounds__(256) void ln_residual_kernel(
    const float* __restrict__ Z,
    const float* __restrict__ gamma, const float* __restrict__ beta,
    const float* __restrict__ alpha, float* __restrict__ out)
{
    const int row = blockIdx.x;
    const int tid = threadIdx.x;
    float4* orow = reinterpret_cast<float4*>(out + (size_t)row * DIM);
    const float4* zrow = reinterpret_cast<const float4*>(Z + (size_t)row * DIM);

    float4 v = orow[tid];

    __shared__ float red1[8];
    __shared__ float red2[8];

    float s = v.x + v.y + v.z + v.w;
#pragma unroll
    for (int o = 16; o > 0; o >>= 1) s += __shfl_xor_sync(0xffffffffu, s, o);
    if ((tid & 31) == 0) red1[tid >> 5] = s;
    __syncthreads();
    float tot = 0.0f;
#pragma unroll
    for (int i = 0; i < 8; i++) tot += red1[i];
    const float mu = tot * (1.0f / (float)DIM);

    const float dx = v.x - mu, dy = v.y - mu, dz = v.z - mu, dw = v.w - mu;
    float ss = dx * dx + dy * dy + dz * dz + dw * dw;
#pragma unroll
    for (int o = 16; o > 0; o >>= 1) ss += __shfl_xor_sync(0xffffffffu, ss, o);
    if ((tid & 31) == 0) red2[tid >> 5] = ss;
    __syncthreads();
    float tot2 = 0.0f;
#pragma unroll
    for (int i = 0; i < 8; i++) tot2 += red2[i];
    const float rstd = rsqrtf(tot2 * (1.0f / (float)DIM) + 1e-5f);

    const float4 g  = reinterpret_cast<const float4*>(gamma)[tid];
    const float4 b  = reinterpret_cast<const float4*>(beta)[tid];
    const float4 al = reinterpret_cast<const float4*>(alpha)[tid];
    const float4 z4 = zrow[tid];

    float4 o4;
    o4.x = z4.x + tanhf(al.x) * (dx * rstd * g.x + b.x);
    o4.y = z4.y + tanhf(al.y) * (dy * rstd * g.y + b.y);
    o4.z = z4.z + tanhf(al.z) * (dz * rstd * g.z + b.z);
    o4.w = z4.w + tanhf(al.w) * (dw * rstd * g.w + b.w);
    orow[tid] = o4;
}

// ---------------- launch --------------------------------------------------------
extern "C" void kernel_launch(void* const* d_in, const int* in_sizes, int n_in,
                              void* d_out, int out_size)
{
    const float* x       = (const float*)d_in[0];
    const float* theta_Q = (const float*)d_in[1];
    const float* W1      = (const float*)d_in[2];
    const float* b1      = (const float*)d_in[3];
    const float* W2      = (const float*)d_in[4];
    const float* b2      = (const float*)d_in[5];
    const float* gamma   = (const float*)d_in[6];
    const float* beta    = (const float*)d_in[7];
    const float* alpha   = (const float*)d_in[8];
    float* out = (float*)d_out;

    float* pz;
    uint16_t *pxh, *pxl, *pzh, *pzl, *phh, *phl;
    uint16_t *pth, *ptl, *pw1h, *pw1l, *pw2h, *pw2l;
    cudaGetSymbolAddress((void**)&pz,   g_z);
    cudaGetSymbolAddress((void**)&pxh,  g_xh);
    cudaGetSymbolAddress((void**)&pxl,  g_xl);
    cudaGetSymbolAddress((void**)&pzh,  g_zh);
    cudaGetSymbolAddress((void**)&pzl,  g_zl);
    cudaGetSymbolAddress((void**)&phh,  g_hh);
    cudaGetSymbolAddress((void**)&phl,  g_hl);
    cudaGetSymbolAddress((void**)&pth,  g_th);
    cudaGetSymbolAddress((void**)&ptl,  g_tl);
    cudaGetSymbolAddress((void**)&pw1h, g_w1h);
    cudaGetSymbolAddress((void**)&pw1l, g_w1l);
    cudaGetSymbolAddress((void**)&pw2h, g_w2h);
    cudaGetSymbolAddress((void**)&pw2l, g_w2l);

    cudaFuncSetAttribute((const void*)gemm_mma<0>, cudaFuncAttributeMaxDynamicSharedMemorySize, SMEM_TOTAL);
    cudaFuncSetAttribute((const void*)gemm_mma<1>, cudaFuncAttributeMaxDynamicSharedMemorySize, SMEM_TOTAL);
    cudaFuncSetAttribute((const void*)gemm_mma<2>, cudaFuncAttributeMaxDynamicSharedMemorySize, SMEM_TOTAL);

    // input conversions (x split) and weight transpose+split
    convert_split_kernel<<<(M_TOK * DIM) / 1024, 256>>>(x, pxh, pxl);
    transpose_split_kernel<<<dim3(DIM / 32, DIM / 32), dim3(32, 8)>>>(theta_Q, pth, ptl, DIM, DIM);
    transpose_split_kernel<<<dim3(HID / 32, DIM / 32), dim3(32, 8)>>>(W1, pw1h, pw1l, DIM, HID);
    transpose_split_kernel<<<dim3(DIM / 32, HID / 32), dim3(32, 8)>>>(W2, pw2h, pw2l, HID, DIM);

    // z = x @ theta   (write z fp32 + split)
    gemm_mma<0><<<dim3(DIM / 128, M_TOK / 128), 256, SMEM_TOTAL>>>(
        pxh, pxl, pth, ptl, nullptr, pz, pzh, pzl, DIM, DIM);
    // h = gelu(z @ W1 + b1)  (write split only)
    gemm_mma<1><<<dim3(HID / 128, M_TOK / 128), 256, SMEM_TOTAL>>>(
        pzh, pzl, pw1h, pw1l, b1, nullptr, phh, phl, DIM, HID);
    // y = h @ W2 + b2  -> d_out fp32
    gemm_mma<2><<<dim3(DIM / 128, M_TOK / 128), 256, SMEM_TOTAL>>>(
        phh, phl, pw2h, pw2l, b2, out, nullptr, nullptr, HID, DIM);

    // out = z + tanh(alpha) * LN(y)
    ln_residual_kernel<<<M_TOK, 256>>>(pz, gamma, beta, alpha, out);
}

// round 9
// speedup vs baseline: 5.6415x; 2.2384x over previous
#include <cuda_runtime.h>
#include <cuda_bf16.h>
#include <math.h>
#include <stdint.h>

// Dims fixed by dataset: B=2,V=8,T=512,D=1024,H=4096 -> M=8192 rows.
#define M_TOK 8192
#define DIM   1024
#define HID   4096

// ---------------- scratch (device globals: sanctioned no-alloc workaround) ----
__device__ float    g_z [(size_t)M_TOK * DIM];   // z fp32 (for residual)
__device__ uint16_t g_xh[(size_t)M_TOK * DIM];
__device__ uint16_t g_xl[(size_t)M_TOK * DIM];
__device__ uint16_t g_zh[(size_t)M_TOK * DIM];   // bf16(z) for GEMM1
__device__ uint16_t g_hh[(size_t)M_TOK * HID];   // bf16(h) for GEMM2
__device__ uint16_t g_th [(size_t)DIM * DIM];    // theta^T hi/lo [N=D,K=D]
__device__ uint16_t g_tl [(size_t)DIM * DIM];
__device__ uint16_t g_w1h[(size_t)HID * DIM];    // W1^T hi [H,D]
__device__ uint16_t g_w2h[(size_t)DIM * HID];    // W2^T hi [D,H]

// ---------------- helpers -------------------------------------------------------
__device__ __forceinline__ uint32_t smem_u32(const void* p) {
    uint32_t a;
    asm("{ .reg .u64 t; cvta.to.shared.u64 t, %1; cvt.u32.u64 %0, t; }" : "=r"(a) : "l"(p));
    return a;
}

__device__ __forceinline__ float gelu_exact(float v) {
    return 0.5f * v * (1.0f + erff(v * 0.70710678118654752f));
}

__device__ __forceinline__ void split_bf(float v, uint16_t& h, uint16_t& l) {
    __nv_bfloat16 bh = __float2bfloat16_rn(v);
    float fh = __bfloat162float(bh);
    __nv_bfloat16 bl = __float2bfloat16_rn(v - fh);
    h = *reinterpret_cast<uint16_t*>(&bh);
    l = *reinterpret_cast<uint16_t*>(&bl);
}

__device__ __forceinline__ uint16_t to_bf(float v) {
    __nv_bfloat16 b = __float2bfloat16_rn(v);
    return *reinterpret_cast<uint16_t*>(&b);
}

__device__ __forceinline__ void ldsm4(uint32_t (&r)[4], uint32_t addr) {
    asm volatile("ldmatrix.sync.aligned.m8n8.x4.shared.b16 {%0,%1,%2,%3}, [%4];"
        : "=r"(r[0]), "=r"(r[1]), "=r"(r[2]), "=r"(r[3]) : "r"(addr));
}

__device__ __forceinline__ void mma_bf16(float (&c)[4], const uint32_t (&a)[4],
                                         uint32_t b0, uint32_t b1) {
    asm volatile(
        "mma.sync.aligned.m16n8k16.row.col.f32.bf16.bf16.f32 "
        "{%0,%1,%2,%3}, {%4,%5,%6,%7}, {%8,%9}, {%0,%1,%2,%3};"
        : "+f"(c[0]), "+f"(c[1]), "+f"(c[2]), "+f"(c[3])
        : "r"(a[0]), "r"(a[1]), "r"(a[2]), "r"(a[3]), "r"(b0), "r"(b1));
}

#define CP16(dst, src) \
    asm volatile("cp.async.cg.shared.global [%0], [%1], 16;" :: "r"(dst), "l"(src))
#define CP_COMMIT() asm volatile("cp.async.commit_group;")
#define CP_WAIT2()  asm volatile("cp.async.wait_group 2;")

// ---------------- pre-pass kernels ---------------------------------------------
__global__ __launch_bounds__(256) void convert_split_kernel(
    const float* __restrict__ in, uint16_t* __restrict__ hi, uint16_t* __restrict__ lo)
{
    size_t i = ((size_t)blockIdx.x * 256 + threadIdx.x) * 4;
    float4 v = *reinterpret_cast<const float4*>(in + i);
    ushort4 h, l;
    split_bf(v.x, h.x, l.x);
    split_bf(v.y, h.y, l.y);
    split_bf(v.z, h.z, l.z);
    split_bf(v.w, h.w, l.w);
    *reinterpret_cast<ushort4*>(hi + i) = h;
    *reinterpret_cast<ushort4*>(lo + i) = l;
}

// W is [K,N] fp32 row-major; outputs W^T as [N,K] bf16-bits (hi, optional lo).
template <bool WRITE_LO>
__global__ __launch_bounds__(256) void transpose_split_kernel(
    const float* __restrict__ W, uint16_t* __restrict__ oh, uint16_t* __restrict__ ol,
    int K, int N)
{
    __shared__ float tile[32][33];
    const int tx = threadIdx.x, ty = threadIdx.y;
    const int n0 = blockIdx.x * 32, k0 = blockIdx.y * 32;
#pragma unroll
    for (int i = 0; i < 4; i++)
        tile[ty + i * 8][tx] = W[(size_t)(k0 + ty + i * 8) * N + (n0 + tx)];
    __syncthreads();
#pragma unroll
    for (int i = 0; i < 4; i++) {
        float v = tile[tx][ty + i * 8];
        size_t o = (size_t)(n0 + ty + i * 8) * K + (k0 + tx);
        if (WRITE_LO) {
            uint16_t h, l;
            split_bf(v, h, l);
            oh[o] = h;
            ol[o] = l;
        } else {
            oh[o] = to_bf(v);
        }
    }
}

// ---------------- mma.sync GEMM -------------------------------------------------
// C[M,N] = A @ B^T; A [M,K] bf16 K-major, B [N,K] bf16 K-major.
// TERMS=3: hi/lo split, Ahi*Bhi + Ahi*Blo + Alo*Bhi, fp32 acc.
// TERMS=1: plain bf16 hi only.
// CTA tile 128x128, BK=32, 8 warps (warp tile 32m x 64n), 3-stage cp.async.
// Stage layout TERMS=3 (32KB): Ahi[0,8K) Alo[8K,16K) Bhi[16K,24K) Blo[24K,32K)
// Stage layout TERMS=1 (16KB): Ahi[0,8K) Bhi[8K,16K)
// Tile layout: 128 rows x 64B (32 bf16), 16B chunk c stored at c ^ ((row>>1)&3).
// OP 0: out fp32 + bf16 hi        (z)
// OP 1: +bias, exact GELU, bf16   (h)
// OP 2: +bias, out fp32           (y -> d_out)

template <int OP, int TERMS>
__global__ __launch_bounds__(256, (TERMS == 1 ? 2 : 1)) void gemm_mma(
    const uint16_t* __restrict__ Ah, const uint16_t* __restrict__ Al,
    const uint16_t* __restrict__ Bh, const uint16_t* __restrict__ Bl,
    const float* __restrict__ bias,
    float* __restrict__ outF, uint16_t* __restrict__ outH,
    int K, int N)
{
    constexpr uint32_t STG = (TERMS == 3) ? 32768u : 16384u;
    constexpr uint32_t BOFF = (TERMS == 3) ? 16384u : 8192u;  // B offset within stage

    extern __shared__ __align__(1024) char smem[];
    const uint32_t sb = smem_u32(smem);
    const int tid = threadIdx.x;
    const int wid = tid >> 5, lane = tid & 31;
    const int bx = blockIdx.x, by = blockIdx.y;
    const int NKC = K >> 5;

    const uint16_t* A0h = Ah + (size_t)(by * 128) * K;
    const uint16_t* A0l = (TERMS == 3) ? (Al + (size_t)(by * 128) * K) : nullptr;
    const uint16_t* B0h = Bh + (size_t)(bx * 128) * K;
    const uint16_t* B0l = (TERMS == 3) ? (Bl + (size_t)(bx * 128) * K) : nullptr;

    // staging: 512 chunk-slots per tile, 2 per thread per tile
    const int srow0 = tid >> 2, sc = tid & 3;          // id = tid
    const int srow1 = (tid + 256) >> 2;                // id = tid + 256 (same sc)
    const uint32_t sd0 = (uint32_t)(srow0 * 64 + ((sc ^ ((srow0 >> 1) & 3)) << 4));
    const uint32_t sd1 = (uint32_t)(srow1 * 64 + ((sc ^ ((srow1 >> 1) & 3)) << 4));

    auto issue = [&](int s) {
        if (s < NKC) {
            const int kof = s * 32 + sc * 8;
            const uint32_t base = sb + (uint32_t)(s % 3) * STG;
            const size_t o0 = (size_t)srow0 * K + kof;
            const size_t o1 = (size_t)srow1 * K + kof;
            CP16(base + sd0,        A0h + o0);
            CP16(base + sd1,        A0h + o1);
            CP16(base + BOFF + sd0, B0h + o0);
            CP16(base + BOFF + sd1, B0h + o1);
            if (TERMS == 3) {
                CP16(base + 8192  + sd0, A0l + o0);
                CP16(base + 8192  + sd1, A0l + o1);
                CP16(base + 24576 + sd0, B0l + o0);
                CP16(base + 24576 + sd1, B0l + o1);
            }
        }
        CP_COMMIT();
    };

    issue(0);
    issue(1);
    issue(2);

    const int wm = wid >> 1;          // 0..3 -> m offset wm*32
    const int wn = wid & 1;           // 0..1 -> n offset wn*64
    const int a_r = (lane & 7) + ((lane >> 3) & 1) * 8;
    const int a_c = lane >> 4;
    const int b_r = (lane & 7) + ((lane >> 4) << 3);
    const int b_c = (lane >> 3) & 1;

    float c[2][8][4];
#pragma unroll
    for (int mf = 0; mf < 2; mf++)
#pragma unroll
        for (int nf = 0; nf < 8; nf++)
#pragma unroll
            for (int j = 0; j < 4; j++) c[mf][nf][j] = 0.0f;

    for (int kc = 0; kc < NKC; kc++) {
        CP_WAIT2();
        __syncthreads();
        const uint32_t buf = sb + (uint32_t)(kc % 3) * STG;
#pragma unroll
        for (int ks = 0; ks < 2; ks++) {
            uint32_t ahf[2][4], alf[2][4];
#pragma unroll
            for (int mf = 0; mf < 2; mf++) {
                const int r = wm * 32 + mf * 16 + a_r;
                const uint32_t ad = buf + (uint32_t)(r * 64 +
                                   (((2 * ks + a_c) ^ ((r >> 1) & 3)) << 4));
                ldsm4(ahf[mf], ad);
                if (TERMS == 3) ldsm4(alf[mf], ad + 8192);
            }
#pragma unroll
            for (int g = 0; g < 4; g++) {
                const int r = wn * 64 + g * 16 + b_r;
                const uint32_t bd = buf + BOFF + (uint32_t)(r * 64 +
                                   (((2 * ks + b_c) ^ ((r >> 1) & 3)) << 4));
                uint32_t b[4];
                ldsm4(b, bd);          // Bhi
#pragma unroll
                for (int mf = 0; mf < 2; mf++) {
                    mma_bf16(c[mf][2 * g + 0], ahf[mf], b[0], b[1]);
                    mma_bf16(c[mf][2 * g + 1], ahf[mf], b[2], b[3]);
                    if (TERMS == 3) {
                        mma_bf16(c[mf][2 * g + 0], alf[mf], b[0], b[1]);
                        mma_bf16(c[mf][2 * g + 1], alf[mf], b[2], b[3]);
                    }
                }
                if (TERMS == 3) {
                    ldsm4(b, bd + 8192);   // Blo
#pragma unroll
                    for (int mf = 0; mf < 2; mf++) {
                        mma_bf16(c[mf][2 * g + 0], ahf[mf], b[0], b[1]);
                        mma_bf16(c[mf][2 * g + 1], ahf[mf], b[2], b[3]);
                    }
                }
            }
        }
        __syncthreads();
        issue(kc + 3);
    }

    // ---- epilogue: fragments -> GMEM (coalesced 32B sectors per lane-quad) ----
    const int r0 = by * 128 + wm * 32 + (lane >> 2);
    const int c0 = bx * 128 + wn * 64 + (lane & 3) * 2;

#pragma unroll
    for (int mf = 0; mf < 2; mf++) {
#pragma unroll
        for (int nf = 0; nf < 8; nf++) {
            const int col = c0 + nf * 8;
            float bv0 = 0.0f, bv1 = 0.0f;
            if (OP >= 1) { bv0 = bias[col]; bv1 = bias[col + 1]; }
#pragma unroll
            for (int half = 0; half < 2; half++) {
                const int row = r0 + mf * 16 + half * 8;
                float v0 = c[mf][nf][2 * half + 0];
                float v1 = c[mf][nf][2 * half + 1];
                const size_t o = (size_t)row * N + col;
                if (OP == 0) {
                    *reinterpret_cast<float2*>(outF + o) = make_float2(v0, v1);
                    *reinterpret_cast<uint32_t*>(outH + o) =
                        (uint32_t)to_bf(v0) | ((uint32_t)to_bf(v1) << 16);
                } else if (OP == 1) {
                    v0 = gelu_exact(v0 + bv0);
                    v1 = gelu_exact(v1 + bv1);
                    *reinterpret_cast<uint32_t*>(outH + o) =
                        (uint32_t)to_bf(v0) | ((uint32_t)to_bf(v1) << 16);
                } else {
                    *reinterpret_cast<float2*>(outF + o) = make_float2(v0 + bv0, v1 + bv1);
                }
            }
        }
    }
}

// ---------------- LayerNorm + residual -----------------------------------------
__global__ __launch_bounds__(256) void ln_residual_kernel(
    const float* __restrict__ Z,
    const float* __restrict__ gamma, const float* __restrict__ beta,
    const float* __restrict__ alpha, float* __restrict__ out)
{
    const int row = blockIdx.x;
    const int tid = threadIdx.x;
    float4* orow = reinterpret_cast<float4*>(out + (size_t)row * DIM);
    const float4* zrow = reinterpret_cast<const float4*>(Z + (size_t)row * DIM);

    float4 v = orow[tid];

    __shared__ float red1[8];
    __shared__ float red2[8];

    float s = v.x + v.y + v.z + v.w;
#pragma unroll
    for (int o = 16; o > 0; o >>= 1) s += __shfl_xor_sync(0xffffffffu, s, o);
    if ((tid & 31) == 0) red1[tid >> 5] = s;
    __syncthreads();
    float tot = 0.0f;
#pragma unroll
    for (int i = 0; i < 8; i++) tot += red1[i];
    const float mu = tot * (1.0f / (float)DIM);

    const float dx = v.x - mu, dy = v.y - mu, dz = v.z - mu, dw = v.w - mu;
    float ss = dx * dx + dy * dy + dz * dz + dw * dw;
#pragma unroll
    for (int o = 16; o > 0; o >>= 1) ss += __shfl_xor_sync(0xffffffffu, ss, o);
    if ((tid & 31) == 0) red2[tid >> 5] = ss;
    __syncthreads();
    float tot2 = 0.0f;
#pragma unroll
    for (int i = 0; i < 8; i++) tot2 += red2[i];
    const float rstd = rsqrtf(tot2 * (1.0f / (float)DIM) + 1e-5f);

    const float4 g  = reinterpret_cast<const float4*>(gamma)[tid];
    const float4 b  = reinterpret_cast<const float4*>(beta)[tid];
    const float4 al = reinterpret_cast<const float4*>(alpha)[tid];
    const float4 z4 = zrow[tid];

    float4 o4;
    o4.x = z4.x + tanhf(al.x) * (dx * rstd * g.x + b.x);
    o4.y = z4.y + tanhf(al.y) * (dy * rstd * g.y + b.y);
    o4.z = z4.z + tanhf(al.z) * (dz * rstd * g.z + b.z);
    o4.w = z4.w + tanhf(al.w) * (dw * rstd * g.w + b.w);
    orow[tid] = o4;
}

// ---------------- launch --------------------------------------------------------
extern "C" void kernel_launch(void* const* d_in, const int* in_sizes, int n_in,
                              void* d_out, int out_size)
{
    const float* x       = (const float*)d_in[0];
    const float* theta_Q = (const float*)d_in[1];
    const float* W1      = (const float*)d_in[2];
    const float* b1      = (const float*)d_in[3];
    const float* W2      = (const float*)d_in[4];
    const float* b2      = (const float*)d_in[5];
    const float* gamma   = (const float*)d_in[6];
    const float* beta    = (const float*)d_in[7];
    const float* alpha   = (const float*)d_in[8];
    float* out = (float*)d_out;

    float* pz;
    uint16_t *pxh, *pxl, *pzh, *phh, *pth, *ptl, *pw1h, *pw2h;
    cudaGetSymbolAddress((void**)&pz,   g_z);
    cudaGetSymbolAddress((void**)&pxh,  g_xh);
    cudaGetSymbolAddress((void**)&pxl,  g_xl);
    cudaGetSymbolAddress((void**)&pzh,  g_zh);
    cudaGetSymbolAddress((void**)&phh,  g_hh);
    cudaGetSymbolAddress((void**)&pth,  g_th);
    cudaGetSymbolAddress((void**)&ptl,  g_tl);
    cudaGetSymbolAddress((void**)&pw1h, g_w1h);
    cudaGetSymbolAddress((void**)&pw2h, g_w2h);

    cudaFuncSetAttribute((const void*)gemm_mma<0, 3>, cudaFuncAttributeMaxDynamicSharedMemorySize, 3 * 32768);
    cudaFuncSetAttribute((const void*)gemm_mma<1, 1>, cudaFuncAttributeMaxDynamicSharedMemorySize, 3 * 16384);
    cudaFuncSetAttribute((const void*)gemm_mma<2, 1>, cudaFuncAttributeMaxDynamicSharedMemorySize, 3 * 16384);

    // input conversions (x split) and weight transposes
    convert_split_kernel<<<(M_TOK * DIM) / 1024, 256>>>(x, pxh, pxl);
    transpose_split_kernel<true ><<<dim3(DIM / 32, DIM / 32), dim3(32, 8)>>>(theta_Q, pth, ptl, DIM, DIM);
    transpose_split_kernel<false><<<dim3(HID / 32, DIM / 32), dim3(32, 8)>>>(W1, pw1h, nullptr, DIM, HID);
    transpose_split_kernel<false><<<dim3(DIM / 32, HID / 32), dim3(32, 8)>>>(W2, pw2h, nullptr, HID, DIM);

    // z = x @ theta  (3-term split; write z fp32 + bf16 hi)
    gemm_mma<0, 3><<<dim3(DIM / 128, M_TOK / 128), 256, 3 * 32768>>>(
        pxh, pxl, pth, ptl, nullptr, pz, pzh, DIM, DIM);
    // h = gelu(z @ W1 + b1)  (plain bf16; write bf16 hi)
    gemm_mma<1, 1><<<dim3(HID / 128, M_TOK / 128), 256, 3 * 16384>>>(
        pzh, nullptr, pw1h, nullptr, b1, nullptr, phh, DIM, HID);
    // y = h @ W2 + b2  (plain bf16) -> d_out fp32
    gemm_mma<2, 1><<<dim3(DIM / 128, M_TOK / 128), 256, 3 * 16384>>>(
        phh, nullptr, pw2h, nullptr, b2, out, nullptr, HID, DIM);

    // out = z + tanh(alpha) * LN(y)
    ln_residual_kernel<<<M_TOK, 256>>>(pz, gamma, beta, alpha, out);
}